// round 2
// baseline (speedup 1.0000x reference)
#include <cuda_runtime.h>

#define Bsz 512
#define Ssz 100
#define Hsz 768
#define BS (Bsz*Ssz)
#define LAMBf 0.8f

// ---------------- scratch (allocation-free: __device__ globals) ----------------
__device__ float g_drep[Bsz*Hsz];                 // [B,H] mean over S
__device__ float g_wt[Hsz*Hsz];                   // W_rel^T
__device__ float g_wd[Bsz*Hsz];                   // W_rel @ d_rep per batch
__device__ float g_cont[BS];                      // [B,S]
__device__ float g_rel[BS];                       // [B,S]
__device__ float g_T1[(size_t)BS*Hsz];            // X @ W_sim   (157 MB)
__device__ float g_q[(size_t)Bsz*Ssz*Ssz];        // q matrices  (20.5 MB)

// ---------------- d_rep = mean over S ----------------
__global__ void k_mean(const float* __restrict__ X) {
    int b = blockIdx.x;
    const float* Xb = X + (size_t)b*Ssz*Hsz;
    for (int h = threadIdx.x; h < Hsz; h += blockDim.x) {
        float s = 0.f;
        #pragma unroll 4
        for (int i = 0; i < Ssz; i++) s += Xb[(size_t)i*Hsz + h];
        g_drep[b*Hsz + h] = s * (1.f/Ssz);
    }
}

// ---------------- transpose W_rel -> g_wt ----------------
__global__ void k_transpose(const float* __restrict__ W, float* __restrict__ Wt) {
    __shared__ float tile[32][33];
    int x = blockIdx.x*32 + threadIdx.x;
    int y = blockIdx.y*32 + threadIdx.y;
    #pragma unroll
    for (int dy = 0; dy < 32; dy += 8)
        tile[threadIdx.y+dy][threadIdx.x] = W[(size_t)(y+dy)*Hsz + x];
    __syncthreads();
    x = blockIdx.y*32 + threadIdx.x;
    y = blockIdx.x*32 + threadIdx.y;
    #pragma unroll
    for (int dy = 0; dy < 32; dy += 8)
        Wt[(size_t)(y+dy)*Hsz + x] = tile[threadIdx.x][threadIdx.y+dy];
}

// ---------------- generic fp32 SGEMM: C[M,N] = A[M,K] @ B[K,N] ----------------
// BM=BN=128, BK=16, 256 threads, 8x8 microtile (split 4+4 halves).
// Requires M%128==0, N%128==0, K%16==0. (51200/512 x 768 x 768 all satisfy.)
__global__ __launch_bounds__(256) void k_sgemm(const float* __restrict__ A,
                                               const float* __restrict__ B,
                                               float* __restrict__ C,
                                               int M, int N, int K) {
    __shared__ float As[16][128];   // [k][m]
    __shared__ float Bs[16][128];   // [k][n]
    int tid = threadIdx.x;
    int tx = tid & 15, ty = tid >> 4;

    const float* Ab = A + (size_t)(blockIdx.y*128)*K;
    const float* Bb = B + blockIdx.x*128;

    float acc[8][8] = {};

    int ar = tid >> 2;            // 0..63 (two passes: +0, +64)
    int ac = (tid & 3)*4;         // float4 col within 16-wide k slab
    int br = tid >> 5;            // 0..7 (two passes: +0, +8)
    int bc = (tid & 31)*4;        // float4 col within 128-wide n slab

    for (int k0 = 0; k0 < K; k0 += 16) {
        float4 va0 = *(const float4*)(Ab + (size_t)ar*K      + k0 + ac);
        float4 va1 = *(const float4*)(Ab + (size_t)(ar+64)*K + k0 + ac);
        float4 vb0 = *(const float4*)(Bb + (size_t)(k0+br)*N   + bc);
        float4 vb1 = *(const float4*)(Bb + (size_t)(k0+br+8)*N + bc);
        As[ac+0][ar] = va0.x; As[ac+1][ar] = va0.y; As[ac+2][ar] = va0.z; As[ac+3][ar] = va0.w;
        As[ac+0][ar+64] = va1.x; As[ac+1][ar+64] = va1.y; As[ac+2][ar+64] = va1.z; As[ac+3][ar+64] = va1.w;
        *(float4*)&Bs[br][bc]   = vb0;
        *(float4*)&Bs[br+8][bc] = vb1;
        __syncthreads();
        #pragma unroll
        for (int kk = 0; kk < 16; kk++) {
            float4 a0 = *(const float4*)&As[kk][ty*4];
            float4 a1 = *(const float4*)&As[kk][64 + ty*4];
            float4 b0 = *(const float4*)&Bs[kk][tx*4];
            float4 b1 = *(const float4*)&Bs[kk][64 + tx*4];
            float ra[8] = {a0.x,a0.y,a0.z,a0.w,a1.x,a1.y,a1.z,a1.w};
            float rb[8] = {b0.x,b0.y,b0.z,b0.w,b1.x,b1.y,b1.z,b1.w};
            #pragma unroll
            for (int i = 0; i < 8; i++)
                #pragma unroll
                for (int j = 0; j < 8; j++)
                    acc[i][j] += ra[i]*rb[j];
        }
        __syncthreads();
    }

    float* Cb = C + (size_t)(blockIdx.y*128)*N + blockIdx.x*128;
    #pragma unroll
    for (int i = 0; i < 8; i++) {
        int row = (i < 4) ? (ty*4 + i) : (64 + ty*4 + (i-4));
        *(float4*)(Cb + (size_t)row*N + tx*4)      = make_float4(acc[i][0],acc[i][1],acc[i][2],acc[i][3]);
        *(float4*)(Cb + (size_t)row*N + 64 + tx*4) = make_float4(acc[i][4],acc[i][5],acc[i][6],acc[i][7]);
    }
}

// ---------------- cont & rel: one warp per (b,i) row ----------------
__global__ void k_cont_rel(const float* __restrict__ X, const float* __restrict__ Wc) {
    int row = blockIdx.x*8 + (threadIdx.x >> 5);
    if (row >= BS) return;
    int lane = threadIdx.x & 31;
    int b = row / Ssz;
    const float4* x  = (const float4*)(X + (size_t)row*Hsz);
    const float4* wc = (const float4*)Wc;
    const float4* wd = (const float4*)(g_wd + b*Hsz);
    float sc = 0.f, sr = 0.f;
    #pragma unroll
    for (int c = 0; c < Hsz/128; c++) {
        int k = c*32 + lane;
        float4 xv = x[k], a = wc[k], d = wd[k];
        sc += xv.x*a.x + xv.y*a.y + xv.z*a.z + xv.w*a.w;
        sr += xv.x*d.x + xv.y*d.y + xv.z*d.z + xv.w*d.w;
    }
    #pragma unroll
    for (int o = 16; o; o >>= 1) {
        sc += __shfl_down_sync(0xffffffffu, sc, o);
        sr += __shfl_down_sync(0xffffffffu, sr, o);
    }
    if (!lane) { g_cont[row] = sc; g_rel[row] = sr; }
}

// ---------------- per-batch: sim = T1_b @ X_b^T, fused sigmoid -> q ----------------
__global__ __launch_bounds__(256) void k_sim_q(const float* __restrict__ X,
                                               const int* __restrict__ mask,
                                               const float* __restrict__ bptr) {
    int b = blockIdx.x;
    __shared__ float Ts[100][33];
    __shared__ float Xs[100][33];
    const float* T1b = g_T1 + (size_t)b*Ssz*Hsz;
    const float* Xb  = X    + (size_t)b*Ssz*Hsz;
    int tid = threadIdx.x;
    int tx = tid & 15, ty = tid >> 4;

    int ii[7], jj[7];
    bool iv[7], jv[7];
    #pragma unroll
    for (int s = 0; s < 7; s++) {
        int i = ty + 16*s; iv[s] = (i < Ssz); ii[s] = iv[s] ? i : 0;
        int j = tx + 16*s; jv[s] = (j < Ssz); jj[s] = jv[s] ? j : 0;
    }
    float acc[7][7] = {};

    for (int k0 = 0; k0 < Hsz; k0 += 32) {
        for (int idx = tid; idx < Ssz*32; idx += 256) {
            int r = idx >> 5, c = idx & 31;
            Ts[r][c] = T1b[(size_t)r*Hsz + k0 + c];
            Xs[r][c] = Xb[(size_t)r*Hsz + k0 + c];
        }
        __syncthreads();
        #pragma unroll 4
        for (int kk = 0; kk < 32; kk++) {
            float ra[7], rb[7];
            #pragma unroll
            for (int s = 0; s < 7; s++) { ra[s] = Ts[ii[s]][kk]; rb[s] = Xs[jj[s]][kk]; }
            #pragma unroll
            for (int s = 0; s < 7; s++)
                #pragma unroll
                for (int t = 0; t < 7; t++)
                    acc[s][t] += ra[s]*rb[t];
        }
        __syncthreads();
    }

    float bias = bptr[0];
    #pragma unroll
    for (int s = 0; s < 7; s++) {
        if (!iv[s]) continue;
        int i = ii[s];
        float mi = (float)mask[b*Ssz + i];
        float ri = g_rel[b*Ssz + i];
        float ci = g_cont[b*Ssz + i];
        #pragma unroll
        for (int t = 0; t < 7; t++) {
            if (!jv[t]) continue;
            int j = jj[t];
            float mm = mi * (float)mask[b*Ssz + j];
            float arg = (ri + acc[s][t])*mm + ci + bias;
            float qv = mm / (1.f + __expf(-arg));
            g_q[((size_t)b*Ssz + i)*Ssz + j] = qv;
        }
    }
}

// ---------------- per-batch solve via Neumann series ----------------
// qD is column-stochastic (cols of q normalized by column sums), entries >= 0,
// so ||0.8*qD||_1 = 0.8 and x_{k+1} = y + 0.8*qD*x_k converges at ratio 0.8.
// 100 iterations -> error ~2e-10 << 1e-3 tolerance.
__global__ void k_solve(float* __restrict__ out) {
    int b = blockIdx.x;
    __shared__ float Q[100][101];
    __shared__ float xv[100], xn[100], inv[100];
    int tid = threadIdx.x;
    const float* qb = g_q + (size_t)b*Ssz*Ssz;
    for (int idx = tid; idx < Ssz*Ssz; idx += blockDim.x)
        Q[idx/100][idx%100] = qb[idx];
    __syncthreads();
    if (tid < 100) {
        float s = 0.f;
        for (int i = 0; i < 100; i++) s += Q[i][tid];
        inv[tid] = LAMBf / s;                 // fold lambda into normalization
        xv[tid]  = 1.f/Ssz;
    }
    __syncthreads();
    for (int idx = tid; idx < Ssz*Ssz; idx += blockDim.x) {
        int i = idx/100, j = idx%100;
        Q[i][j] *= inv[j];
    }
    __syncthreads();
    for (int it = 0; it < 100; it++) {
        if (tid < 100) {
            float s = 1.f/Ssz;
            #pragma unroll 4
            for (int j = 0; j < 100; j++) s += Q[tid][j]*xv[j];
            xn[tid] = s;
        }
        __syncthreads();
        if (tid < 100) xv[tid] = xn[tid];
        __syncthreads();
    }
    if (tid < 100) out[(size_t)b*Ssz + tid] = (1.f - LAMBf)*xv[tid];
}

// ---------------- launch ----------------
extern "C" void kernel_launch(void* const* d_in, const int* in_sizes, int n_in,
                              void* d_out, int out_size) {
    const float* X    = (const float*)d_in[0];
    const int*   mask = (const int*)  d_in[1];
    const float* Wc   = (const float*)d_in[2];
    const float* Wsim = (const float*)d_in[3];
    const float* Wrel = (const float*)d_in[4];
    const float* bm   = (const float*)d_in[5];
    float* out = (float*)d_out;

    float *drep, *wt, *wd, *T1;
    cudaGetSymbolAddress((void**)&drep, g_drep);
    cudaGetSymbolAddress((void**)&wt,   g_wt);
    cudaGetSymbolAddress((void**)&wd,   g_wd);
    cudaGetSymbolAddress((void**)&T1,   g_T1);

    // Big GEMM: T1 = X @ W_sim   [51200,768]x[768,768]
    k_sgemm<<<dim3(Hsz/128, BS/128), 256>>>(X, Wsim, T1, BS, Hsz, Hsz);
    // mean, W_rel^T, wd = d_rep @ W_rel^T
    k_mean<<<Bsz, 256>>>(X);
    k_transpose<<<dim3(Hsz/32, Hsz/32), dim3(32, 8)>>>(Wrel, wt);
    k_sgemm<<<dim3(Hsz/128, Bsz/128), 256>>>(drep, wt, wd, Bsz, Hsz, Hsz);
    // cont & rel
    k_cont_rel<<<BS/8, 256>>>(X, Wc);
    // sim + sigmoid -> q
    k_sim_q<<<Bsz, 256>>>(X, mask, bm);
    // batched solve
    k_solve<<<Bsz, 128>>>(out);
}

// round 5
// speedup vs baseline: 2.4071x; 2.4071x over previous
#include <cuda_runtime.h>
#include <cstdint>

#define Bsz 512
#define Ssz 100
#define Hsz 768
#define BS (Bsz*Ssz)
#define LAMBf 0.8f
#define STR 20   // smem lane stride (words); conflict-free for m16n8k8 frag reads

// ---------------- scratch (allocation-free: __device__ globals) ----------------
__device__ float g_drep[Bsz*Hsz];                 // [B,H] mean over S
__device__ float g_wsimT[Hsz*Hsz];                // W_sim^T (N,K row-major)
__device__ float g_wd[Bsz*Hsz];                   // W_rel @ d_rep per batch
__device__ float g_cont[BS];                      // [B,S]
__device__ float g_rel[BS];                       // [B,S]
__device__ float g_T1[(size_t)BS*Hsz];            // X @ W_sim   (157 MB)
__device__ float g_q[(size_t)Bsz*Ssz*Ssz];        // q matrices  (20.5 MB)

// ---------------- helpers ----------------
__device__ __forceinline__ unsigned f2tf(float x) {
    unsigned r; asm("cvt.rna.tf32.f32 %0, %1;" : "=r"(r) : "f"(x)); return r;
}
__device__ __forceinline__ void sts_tf(unsigned* dst, float4 v) {
    uint4 u; u.x = f2tf(v.x); u.y = f2tf(v.y); u.z = f2tf(v.z); u.w = f2tf(v.w);
    *(uint4*)dst = u;
}
__device__ __forceinline__ void mma_tf32(float c[4], unsigned a0, unsigned a1,
                                         unsigned a2, unsigned a3,
                                         unsigned b0, unsigned b1) {
    asm("mma.sync.aligned.m16n8k8.row.col.f32.tf32.tf32.f32 "
        "{%0,%1,%2,%3},{%4,%5,%6,%7},{%8,%9},{%0,%1,%2,%3};"
        : "+f"(c[0]), "+f"(c[1]), "+f"(c[2]), "+f"(c[3])
        : "r"(a0), "r"(a1), "r"(a2), "r"(a3), "r"(b0), "r"(b1));
}

// ---------------- d_rep = mean over S ----------------
__global__ void k_mean(const float* __restrict__ X) {
    int b = blockIdx.x;
    const float* Xb = X + (size_t)b*Ssz*Hsz;
    for (int h = threadIdx.x; h < Hsz; h += blockDim.x) {
        float s = 0.f;
        #pragma unroll 4
        for (int i = 0; i < Ssz; i++) s += Xb[(size_t)i*Hsz + h];
        g_drep[b*Hsz + h] = s * (1.f/Ssz);
    }
}

// ---------------- transpose (768x768) ----------------
__global__ void k_transpose(const float* __restrict__ W, float* __restrict__ Wt) {
    __shared__ float tile[32][33];
    int x = blockIdx.x*32 + threadIdx.x;
    int y = blockIdx.y*32 + threadIdx.y;
    #pragma unroll
    for (int dy = 0; dy < 32; dy += 8)
        tile[threadIdx.y+dy][threadIdx.x] = W[(size_t)(y+dy)*Hsz + x];
    __syncthreads();
    x = blockIdx.y*32 + threadIdx.x;
    y = blockIdx.x*32 + threadIdx.y;
    #pragma unroll
    for (int dy = 0; dy < 32; dy += 8)
        Wt[(size_t)(y+dy)*Hsz + x] = tile[threadIdx.x][threadIdx.y+dy];
}

// ---------------- tf32 NT GEMM: C[M,N] = A[M,K] @ B[N,K]^T ----------------
// BM=BN=128, BK=16, 256 threads (8 warps as 2x4; warp tile 64x32).
// Requires M%128==0, N%128==0, K%16==0.
__global__ __launch_bounds__(256,2) void k_gemm_nt(const float* __restrict__ A,
                                                   const float* __restrict__ B,
                                                   float* __restrict__ C,
                                                   int M, int N, int K) {
    __shared__ unsigned As[128*STR];
    __shared__ unsigned Bs[128*STR];
    int tid  = threadIdx.x;
    int warp = tid >> 5, lane = tid & 31;
    int grp  = lane >> 2, qid = lane & 3;
    int m_off = (warp >> 2)*64, n_off = (warp & 3)*32;

    const float* Ab = A + (size_t)(blockIdx.y*128)*K;
    const float* Bb = B + (size_t)(blockIdx.x*128)*K;

    int lr = tid >> 2;          // 0..63 (+64 second half)
    int lc = (tid & 3)*4;       // float4 col in 16-wide k slab

    float acc[4][4][4] = {};

    float4 pa0 = *(const float4*)(Ab + (size_t)lr*K      + lc);
    float4 pa1 = *(const float4*)(Ab + (size_t)(lr+64)*K + lc);
    float4 pb0 = *(const float4*)(Bb + (size_t)lr*K      + lc);
    float4 pb1 = *(const float4*)(Bb + (size_t)(lr+64)*K + lc);

    int kt = 0;
    for (;;) {
        sts_tf(As + lr*STR + lc,      pa0);
        sts_tf(As + (lr+64)*STR + lc, pa1);
        sts_tf(Bs + lr*STR + lc,      pb0);
        sts_tf(Bs + (lr+64)*STR + lc, pb1);
        __syncthreads();

        kt += 16;
        bool more = (kt < K);
        if (more) {
            pa0 = *(const float4*)(Ab + (size_t)lr*K      + kt + lc);
            pa1 = *(const float4*)(Ab + (size_t)(lr+64)*K + kt + lc);
            pb0 = *(const float4*)(Bb + (size_t)lr*K      + kt + lc);
            pb1 = *(const float4*)(Bb + (size_t)(lr+64)*K + kt + lc);
        }

        #pragma unroll
        for (int ka = 0; ka < 2; ka++) {
            int kb = ka*8;
            unsigned af[4][4], bf[4][2];
            #pragma unroll
            for (int mt = 0; mt < 4; mt++) {
                const unsigned* p = As + (m_off + mt*16 + grp)*STR + kb + qid;
                af[mt][0] = p[0]; af[mt][1] = p[8*STR]; af[mt][2] = p[4]; af[mt][3] = p[8*STR+4];
            }
            #pragma unroll
            for (int nt = 0; nt < 4; nt++) {
                const unsigned* p = Bs + (n_off + nt*8 + grp)*STR + kb + qid;
                bf[nt][0] = p[0]; bf[nt][1] = p[4];
            }
            #pragma unroll
            for (int mt = 0; mt < 4; mt++)
                #pragma unroll
                for (int nt = 0; nt < 4; nt++)
                    mma_tf32(acc[mt][nt], af[mt][0],af[mt][1],af[mt][2],af[mt][3],
                             bf[nt][0], bf[nt][1]);
        }
        if (!more) break;
        __syncthreads();
    }

    float* Cb = C + (size_t)(blockIdx.y*128)*N + blockIdx.x*128;
    #pragma unroll
    for (int mt = 0; mt < 4; mt++) {
        int r = m_off + mt*16 + grp;
        #pragma unroll
        for (int nt = 0; nt < 4; nt++) {
            int c = n_off + nt*8 + qid*2;
            *(float2*)(Cb + (size_t)r*N + c)     = make_float2(acc[mt][nt][0], acc[mt][nt][1]);
            *(float2*)(Cb + (size_t)(r+8)*N + c) = make_float2(acc[mt][nt][2], acc[mt][nt][3]);
        }
    }
}

// ---------------- cont & rel: one warp per (b,i) row ----------------
__global__ void k_cont_rel(const float* __restrict__ X, const float* __restrict__ Wc) {
    int row = blockIdx.x*8 + (threadIdx.x >> 5);
    if (row >= BS) return;
    int lane = threadIdx.x & 31;
    int b = row / Ssz;
    const float4* x  = (const float4*)(X + (size_t)row*Hsz);
    const float4* wc = (const float4*)Wc;
    const float4* wd = (const float4*)(g_wd + b*Hsz);
    float sc = 0.f, sr = 0.f;
    #pragma unroll
    for (int c = 0; c < Hsz/128; c++) {
        int k = c*32 + lane;
        float4 xv = x[k], a = wc[k], d = wd[k];
        sc += xv.x*a.x + xv.y*a.y + xv.z*a.z + xv.w*a.w;
        sr += xv.x*d.x + xv.y*d.y + xv.z*d.z + xv.w*d.w;
    }
    #pragma unroll
    for (int o = 16; o; o >>= 1) {
        sc += __shfl_down_sync(0xffffffffu, sc, o);
        sr += __shfl_down_sync(0xffffffffu, sr, o);
    }
    if (!lane) { g_cont[row] = sc; g_rel[row] = sr; }
}

// ---------------- per-batch sim = T1_b @ X_b^T via tf32 mma, fused sigmoid -> q ----
__global__ __launch_bounds__(256,2) void k_sim_q_mma(const float* __restrict__ X,
                                                     const int* __restrict__ mask,
                                                     const float* __restrict__ bptr) {
    __shared__ unsigned As[128*STR];
    __shared__ unsigned Bs[128*STR];
    __shared__ float cont_s[Ssz], rel_s[Ssz], mask_s[Ssz];

    int b = blockIdx.x;
    const float* T1b = g_T1 + (size_t)b*Ssz*Hsz;
    const float* Xb  = X    + (size_t)b*Ssz*Hsz;

    int tid  = threadIdx.x;
    int warp = tid >> 5, lane = tid & 31;
    int grp  = lane >> 2, qid = lane & 3;
    int m_off = (warp >> 2)*64, n_off = (warp & 3)*32;

    if (tid < Ssz) {
        cont_s[tid] = g_cont[b*Ssz + tid];
        rel_s[tid]  = g_rel[b*Ssz + tid];
        mask_s[tid] = (float)mask[b*Ssz + tid];
    }

    int lr = tid >> 2;
    int lc = (tid & 3)*4;
    int r0 = (lr      < Ssz) ? lr      : Ssz-1;   // clamp: rows >=100 are dummies
    int r1 = (lr + 64 < Ssz) ? lr + 64 : Ssz-1;

    float acc[4][4][4] = {};

    float4 pa0 = *(const float4*)(T1b + (size_t)r0*Hsz + lc);
    float4 pa1 = *(const float4*)(T1b + (size_t)r1*Hsz + lc);
    float4 pb0 = *(const float4*)(Xb  + (size_t)r0*Hsz + lc);
    float4 pb1 = *(const float4*)(Xb  + (size_t)r1*Hsz + lc);

    int kt = 0;
    for (;;) {
        sts_tf(As + lr*STR + lc,      pa0);
        sts_tf(As + (lr+64)*STR + lc, pa1);
        sts_tf(Bs + lr*STR + lc,      pb0);
        sts_tf(Bs + (lr+64)*STR + lc, pb1);
        __syncthreads();

        kt += 16;
        bool more = (kt < Hsz);
        if (more) {
            pa0 = *(const float4*)(T1b + (size_t)r0*Hsz + kt + lc);
            pa1 = *(const float4*)(T1b + (size_t)r1*Hsz + kt + lc);
            pb0 = *(const float4*)(Xb  + (size_t)r0*Hsz + kt + lc);
            pb1 = *(const float4*)(Xb  + (size_t)r1*Hsz + kt + lc);
        }

        #pragma unroll
        for (int ka = 0; ka < 2; ka++) {
            int kb = ka*8;
            unsigned af[4][4], bf[4][2];
            #pragma unroll
            for (int mt = 0; mt < 4; mt++) {
                const unsigned* p = As + (m_off + mt*16 + grp)*STR + kb + qid;
                af[mt][0] = p[0]; af[mt][1] = p[8*STR]; af[mt][2] = p[4]; af[mt][3] = p[8*STR+4];
            }
            #pragma unroll
            for (int nt = 0; nt < 4; nt++) {
                const unsigned* p = Bs + (n_off + nt*8 + grp)*STR + kb + qid;
                bf[nt][0] = p[0]; bf[nt][1] = p[4];
            }
            #pragma unroll
            for (int mt = 0; mt < 4; mt++)
                #pragma unroll
                for (int nt = 0; nt < 4; nt++)
                    mma_tf32(acc[mt][nt], af[mt][0],af[mt][1],af[mt][2],af[mt][3],
                             bf[nt][0], bf[nt][1]);
        }
        if (!more) break;
        __syncthreads();
    }

    float bias = bptr[0];
    float* qb = g_q + (size_t)b*Ssz*Ssz;
    #pragma unroll
    for (int mt = 0; mt < 4; mt++) {
        int i0 = m_off + mt*16 + grp;
        #pragma unroll
        for (int nt = 0; nt < 4; nt++) {
            int j = n_off + nt*8 + qid*2;    // j even; if j<100 then j+1<=99 too
            if (j >= Ssz) continue;
            float mj0 = mask_s[j], mj1 = mask_s[j+1];
            #pragma unroll
            for (int h = 0; h < 2; h++) {
                int i = i0 + h*8;
                if (i >= Ssz) continue;
                float mi = mask_s[i], ri = rel_s[i], ci = cont_s[i];
                float mm0 = mi*mj0, mm1 = mi*mj1;
                float a0 = (ri + acc[mt][nt][h*2+0])*mm0 + ci + bias;
                float a1 = (ri + acc[mt][nt][h*2+1])*mm1 + ci + bias;
                float q0 = mm0 / (1.f + __expf(-a0));
                float q1 = mm1 / (1.f + __expf(-a1));
                *(float2*)(qb + (size_t)i*Ssz + j) = make_float2(q0, q1);
            }
        }
    }
}

// ---------------- per-batch solve via Neumann series ----------------
// qD is column-stochastic => ||0.8 qD||_1 = 0.8; 48 iters -> err ~2e-5 << 1e-3.
__global__ void k_solve(float* __restrict__ out) {
    int b = blockIdx.x;
    __shared__ float Q[100][101];
    __shared__ float xv[100], xn[100], inv[100];
    int tid = threadIdx.x;
    const float* qb = g_q + (size_t)b*Ssz*Ssz;
    for (int idx = tid; idx < Ssz*Ssz; idx += blockDim.x)
        Q[idx/100][idx%100] = qb[idx];
    __syncthreads();
    if (tid < 100) {
        float s = 0.f;
        for (int i = 0; i < 100; i++) s += Q[i][tid];
        inv[tid] = LAMBf / s;
        xv[tid]  = 1.f/Ssz;
    }
    __syncthreads();
    for (int idx = tid; idx < Ssz*Ssz; idx += blockDim.x) {
        int i = idx/100, j = idx%100;
        Q[i][j] *= inv[j];
    }
    __syncthreads();
    for (int it = 0; it < 48; it++) {
        if (tid < 100) {
            float s = 1.f/Ssz;
            #pragma unroll 4
            for (int j = 0; j < 100; j++) s += Q[tid][j]*xv[j];
            xn[tid] = s;
        }
        __syncthreads();
        if (tid < 100) xv[tid] = xn[tid];
        __syncthreads();
    }
    if (tid < 100) out[(size_t)b*Ssz + tid] = (1.f - LAMBf)*xv[tid];
}

// ---------------- launch ----------------
extern "C" void kernel_launch(void* const* d_in, const int* in_sizes, int n_in,
                              void* d_out, int out_size) {
    const float* X    = (const float*)d_in[0];
    const int*   mask = (const int*)  d_in[1];
    const float* Wc   = (const float*)d_in[2];
    const float* Wsim = (const float*)d_in[3];
    const float* Wrel = (const float*)d_in[4];
    const float* bm   = (const float*)d_in[5];
    float* out = (float*)d_out;

    float *drep, *wsimT, *wd, *T1;
    cudaGetSymbolAddress((void**)&drep,  g_drep);
    cudaGetSymbolAddress((void**)&wsimT, g_wsimT);
    cudaGetSymbolAddress((void**)&wd,    g_wd);
    cudaGetSymbolAddress((void**)&T1,    g_T1);

    // W_sim^T (so big GEMM is NT form)
    k_transpose<<<dim3(Hsz/32, Hsz/32), dim3(32, 8)>>>(Wsim, wsimT);
    // T1 = X @ W_sim = X @ (WsimT)^T   [51200,768] x [768,768]
    k_gemm_nt<<<dim3(Hsz/128, BS/128), 256>>>(X, wsimT, T1, BS, Hsz, Hsz);
    // d_rep, wd = drep @ Wrel^T (Wrel is already [N,K] for NT form)
    k_mean<<<Bsz, 256>>>(X);
    k_gemm_nt<<<dim3(Hsz/128, Bsz/128), 256>>>(drep, Wrel, wd, Bsz, Hsz, Hsz);
    // cont & rel
    k_cont_rel<<<BS/8, 256>>>(X, Wc);
    // sim + sigmoid -> q (tensorized, fused epilogue)
    k_sim_q_mma<<<Bsz, 256>>>(X, mask, bm);
    // batched solve
    k_solve<<<Bsz, 128>>>(out);
}

// round 6
// speedup vs baseline: 2.6179x; 1.0876x over previous
#include <cuda_runtime.h>
#include <cstdint>

#define Bsz 512
#define Ssz 100
#define Hsz 768
#define BS (Bsz*Ssz)
#define LAMBf 0.8f
#define STR 20   // smem row stride in words; conflict-free for m16n8k8 frag reads

// ---------------- scratch (allocation-free: __device__ globals) ----------------
__device__ float g_drep[Bsz*Hsz];
__device__ float g_wsimT[Hsz*Hsz];
__device__ float g_wd[Bsz*Hsz];
__device__ float g_cont[BS];
__device__ float g_rel[BS];
__device__ float g_T1[(size_t)BS*Hsz];            // 157 MB
__device__ float g_q[(size_t)Bsz*Ssz*Ssz];        // 20.5 MB

// ---------------- helpers ----------------
__device__ __forceinline__ void cpa16(uint32_t dst, const void* src) {
    asm volatile("cp.async.cg.shared.global [%0], [%1], 16;" :: "r"(dst), "l"(src));
}
__device__ __forceinline__ void cp_commit() { asm volatile("cp.async.commit_group;"); }
template<int N> __device__ __forceinline__ void cp_wait() {
    asm volatile("cp.async.wait_group %0;" :: "n"(N));
}
// tf32 mma: raw fp32 bits are valid tf32 operands (low mantissa bits ignored by HW)
__device__ __forceinline__ void mma_tf32(float c[4], unsigned a0, unsigned a1,
                                         unsigned a2, unsigned a3,
                                         unsigned b0, unsigned b1) {
    asm("mma.sync.aligned.m16n8k8.row.col.f32.tf32.tf32.f32 "
        "{%0,%1,%2,%3},{%4,%5,%6,%7},{%8,%9},{%0,%1,%2,%3};"
        : "+f"(c[0]), "+f"(c[1]), "+f"(c[2]), "+f"(c[3])
        : "r"(a0), "r"(a1), "r"(a2), "r"(a3), "r"(b0), "r"(b1));
}

// ---------------- d_rep = mean over S ----------------
__global__ void k_mean(const float* __restrict__ X) {
    int b = blockIdx.x;
    const float* Xb = X + (size_t)b*Ssz*Hsz;
    for (int h = threadIdx.x; h < Hsz; h += blockDim.x) {
        float s = 0.f;
        #pragma unroll 4
        for (int i = 0; i < Ssz; i++) s += Xb[(size_t)i*Hsz + h];
        g_drep[b*Hsz + h] = s * (1.f/Ssz);
    }
}

// ---------------- transpose (768x768) ----------------
__global__ void k_transpose(const float* __restrict__ W, float* __restrict__ Wt) {
    __shared__ float tile[32][33];
    int x = blockIdx.x*32 + threadIdx.x;
    int y = blockIdx.y*32 + threadIdx.y;
    #pragma unroll
    for (int dy = 0; dy < 32; dy += 8)
        tile[threadIdx.y+dy][threadIdx.x] = W[(size_t)(y+dy)*Hsz + x];
    __syncthreads();
    x = blockIdx.y*32 + threadIdx.x;
    y = blockIdx.x*32 + threadIdx.y;
    #pragma unroll
    for (int dy = 0; dy < 32; dy += 8)
        Wt[(size_t)(y+dy)*Hsz + x] = tile[threadIdx.x][threadIdx.y+dy];
}

// ---------------- warp-tile compute: 64x32 warp tile over 16-k slab ----------------
__device__ __forceinline__ void mma_slab_128(const unsigned* As, const unsigned* Bs,
                                             int m_off, int n_off, int grp, int qid,
                                             float acc[4][4][4]) {
    #pragma unroll
    for (int ka = 0; ka < 2; ka++) {
        int kb = ka*8;
        unsigned af[4][4], bf[4][2];
        #pragma unroll
        for (int mt = 0; mt < 4; mt++) {
            const unsigned* p = As + (m_off + mt*16 + grp)*STR + kb + qid;
            af[mt][0] = p[0]; af[mt][1] = p[8*STR]; af[mt][2] = p[4]; af[mt][3] = p[8*STR+4];
        }
        #pragma unroll
        for (int nt = 0; nt < 4; nt++) {
            const unsigned* p = Bs + (n_off + nt*8 + grp)*STR + kb + qid;
            bf[nt][0] = p[0]; bf[nt][1] = p[4];
        }
        #pragma unroll
        for (int mt = 0; mt < 4; mt++)
            #pragma unroll
            for (int nt = 0; nt < 4; nt++)
                mma_tf32(acc[mt][nt], af[mt][0],af[mt][1],af[mt][2],af[mt][3],
                         bf[nt][0], bf[nt][1]);
    }
}

// ---------------- tf32 NT GEMM, cp.async 2-stage: C[M,N] = A[M,K] @ B[N,K]^T ------
// BM=BN=128, BK=16, 256 threads (8 warps 2x4, warp tile 64x32). M%128==N%128==K%16==0.
__global__ __launch_bounds__(256,2) void k_gemm_nt(const float* __restrict__ A,
                                                   const float* __restrict__ B,
                                                   float* __restrict__ C,
                                                   int M, int N, int K) {
    __shared__ float As[2][128*STR];
    __shared__ float Bs[2][128*STR];
    int tid  = threadIdx.x;
    int warp = tid >> 5, lane = tid & 31;
    int grp  = lane >> 2, qid = lane & 3;
    int m_off = (warp >> 2)*64, n_off = (warp & 3)*32;

    const float* Ab = A + (size_t)(blockIdx.y*128)*K;
    const float* Bb = B + (size_t)(blockIdx.x*128)*K;

    int r0 = tid >> 2;          // 0..63 (+64 second task)
    int c4 = (tid & 3)*4;       // word col within 16-wide slab

    uint32_t sA0 = (uint32_t)__cvta_generic_to_shared(&As[0][0]) + (r0*STR + c4)*4;
    uint32_t sB0 = (uint32_t)__cvta_generic_to_shared(&Bs[0][0]) + (r0*STR + c4)*4;
    const uint32_t stage = 128*STR*4;
    const uint32_t rowsk = 64*STR*4;

    float acc[4][4][4] = {};
    int ntiles = K/16;

    // prologue: stage 0
    cpa16(sA0,         Ab + (size_t)r0*K      + c4);
    cpa16(sA0 + rowsk, Ab + (size_t)(r0+64)*K + c4);
    cpa16(sB0,         Bb + (size_t)r0*K      + c4);
    cpa16(sB0 + rowsk, Bb + (size_t)(r0+64)*K + c4);
    cp_commit();

    for (int t = 0; t < ntiles; t++) {
        int s = t & 1;
        if (t+1 < ntiles) {
            int kt = (t+1)*16;
            uint32_t ds = (t+1)&1 ? stage : 0;
            cpa16(sA0 + ds,         Ab + (size_t)r0*K      + kt + c4);
            cpa16(sA0 + ds + rowsk, Ab + (size_t)(r0+64)*K + kt + c4);
            cpa16(sB0 + ds,         Bb + (size_t)r0*K      + kt + c4);
            cpa16(sB0 + ds + rowsk, Bb + (size_t)(r0+64)*K + kt + c4);
            cp_commit();
            cp_wait<1>();
        } else {
            cp_wait<0>();
        }
        __syncthreads();
        mma_slab_128((const unsigned*)As[s], (const unsigned*)Bs[s],
                     m_off, n_off, grp, qid, acc);
        __syncthreads();
    }

    float* Cb = C + (size_t)(blockIdx.y*128)*N + blockIdx.x*128;
    #pragma unroll
    for (int mt = 0; mt < 4; mt++) {
        int r = m_off + mt*16 + grp;
        #pragma unroll
        for (int nt = 0; nt < 4; nt++) {
            int c = n_off + nt*8 + qid*2;
            *(float2*)(Cb + (size_t)r*N + c)     = make_float2(acc[mt][nt][0], acc[mt][nt][1]);
            *(float2*)(Cb + (size_t)(r+8)*N + c) = make_float2(acc[mt][nt][2], acc[mt][nt][3]);
        }
    }
}

// ---------------- BM=32 variant for the thin wd GEMM (M=512 -> grid 96) ----------
// 8 warps in 1x8, warp tile 32x16.
__global__ __launch_bounds__(256,2) void k_gemm_nt32(const float* __restrict__ A,
                                                     const float* __restrict__ B,
                                                     float* __restrict__ C,
                                                     int M, int N, int K) {
    __shared__ float As[2][32*STR];
    __shared__ float Bs[2][128*STR];
    int tid  = threadIdx.x;
    int warp = tid >> 5, lane = tid & 31;
    int grp  = lane >> 2, qid = lane & 3;
    int n_off = warp*16;

    const float* Ab = A + (size_t)(blockIdx.y*32)*K;
    const float* Bb = B + (size_t)(blockIdx.x*128)*K;

    int r0 = tid >> 2;          // 0..63
    int c4 = (tid & 3)*4;

    uint32_t sA0 = (uint32_t)__cvta_generic_to_shared(&As[0][0]) + (r0*STR + c4)*4;
    uint32_t sB0 = (uint32_t)__cvta_generic_to_shared(&Bs[0][0]) + (r0*STR + c4)*4;
    const uint32_t stageA = 32*STR*4, stageB = 128*STR*4;
    const uint32_t rowsk = 64*STR*4;
    bool doA = (tid < 128);     // A: 32 rows x 4 cols = 128 tasks

    float acc[2][2][4] = {};
    int ntiles = K/16;

    if (doA) cpa16(sA0, Ab + (size_t)r0*K + c4);
    cpa16(sB0,         Bb + (size_t)r0*K      + c4);
    cpa16(sB0 + rowsk, Bb + (size_t)(r0+64)*K + c4);
    cp_commit();

    for (int t = 0; t < ntiles; t++) {
        int s = t & 1;
        if (t+1 < ntiles) {
            int kt = (t+1)*16;
            uint32_t dA = (t+1)&1 ? stageA : 0;
            uint32_t dB = (t+1)&1 ? stageB : 0;
            if (doA) cpa16(sA0 + dA, Ab + (size_t)r0*K + kt + c4);
            cpa16(sB0 + dB,         Bb + (size_t)r0*K      + kt + c4);
            cpa16(sB0 + dB + rowsk, Bb + (size_t)(r0+64)*K + kt + c4);
            cp_commit();
            cp_wait<1>();
        } else {
            cp_wait<0>();
        }
        __syncthreads();
        const unsigned* Au = (const unsigned*)As[s];
        const unsigned* Bu = (const unsigned*)Bs[s];
        #pragma unroll
        for (int ka = 0; ka < 2; ka++) {
            int kb = ka*8;
            unsigned af[2][4], bf[2][2];
            #pragma unroll
            for (int mt = 0; mt < 2; mt++) {
                const unsigned* p = Au + (mt*16 + grp)*STR + kb + qid;
                af[mt][0] = p[0]; af[mt][1] = p[8*STR]; af[mt][2] = p[4]; af[mt][3] = p[8*STR+4];
            }
            #pragma unroll
            for (int nt = 0; nt < 2; nt++) {
                const unsigned* p = Bu + (n_off + nt*8 + grp)*STR + kb + qid;
                bf[nt][0] = p[0]; bf[nt][1] = p[4];
            }
            #pragma unroll
            for (int mt = 0; mt < 2; mt++)
                #pragma unroll
                for (int nt = 0; nt < 2; nt++)
                    mma_tf32(acc[mt][nt], af[mt][0],af[mt][1],af[mt][2],af[mt][3],
                             bf[nt][0], bf[nt][1]);
        }
        __syncthreads();
    }

    float* Cb = C + (size_t)(blockIdx.y*32)*N + blockIdx.x*128;
    #pragma unroll
    for (int mt = 0; mt < 2; mt++) {
        int r = mt*16 + grp;
        #pragma unroll
        for (int nt = 0; nt < 2; nt++) {
            int c = n_off + nt*8 + qid*2;
            *(float2*)(Cb + (size_t)r*N + c)     = make_float2(acc[mt][nt][0], acc[mt][nt][1]);
            *(float2*)(Cb + (size_t)(r+8)*N + c) = make_float2(acc[mt][nt][2], acc[mt][nt][3]);
        }
    }
}

// ---------------- cont & rel: one warp per (b,i) row ----------------
__global__ void k_cont_rel(const float* __restrict__ X, const float* __restrict__ Wc) {
    int row = blockIdx.x*8 + (threadIdx.x >> 5);
    if (row >= BS) return;
    int lane = threadIdx.x & 31;
    int b = row / Ssz;
    const float4* x  = (const float4*)(X + (size_t)row*Hsz);
    const float4* wc = (const float4*)Wc;
    const float4* wd = (const float4*)(g_wd + b*Hsz);
    float sc = 0.f, sr = 0.f;
    #pragma unroll
    for (int c = 0; c < Hsz/128; c++) {
        int k = c*32 + lane;
        float4 xv = x[k], a = wc[k], d = wd[k];
        sc += xv.x*a.x + xv.y*a.y + xv.z*a.z + xv.w*a.w;
        sr += xv.x*d.x + xv.y*d.y + xv.z*d.z + xv.w*d.w;
    }
    #pragma unroll
    for (int o = 16; o; o >>= 1) {
        sc += __shfl_down_sync(0xffffffffu, sc, o);
        sr += __shfl_down_sync(0xffffffffu, sr, o);
    }
    if (!lane) { g_cont[row] = sc; g_rel[row] = sr; }
}

// ---------------- per-batch sim = T1_b @ X_b^T (tf32 mma, cp.async), fused q -------
__global__ __launch_bounds__(256,2) void k_sim_q_mma(const float* __restrict__ X,
                                                     const int* __restrict__ mask,
                                                     const float* __restrict__ bptr) {
    __shared__ float As[2][128*STR];
    __shared__ float Bs[2][128*STR];
    __shared__ float cont_s[Ssz], rel_s[Ssz], mask_s[Ssz];

    int b = blockIdx.x;
    const float* T1b = g_T1 + (size_t)b*Ssz*Hsz;
    const float* Xb  = X    + (size_t)b*Ssz*Hsz;

    int tid  = threadIdx.x;
    int warp = tid >> 5, lane = tid & 31;
    int grp  = lane >> 2, qid = lane & 3;
    int m_off = (warp >> 2)*64, n_off = (warp & 3)*32;

    if (tid < Ssz) {
        cont_s[tid] = g_cont[b*Ssz + tid];
        rel_s[tid]  = g_rel[b*Ssz + tid];
        mask_s[tid] = (float)mask[b*Ssz + tid];
    }

    int r0 = tid >> 2;
    int c4 = (tid & 3)*4;
    int gr0 = (r0      < Ssz) ? r0      : Ssz-1;   // clamp dummies
    int gr1 = (r0 + 64 < Ssz) ? r0 + 64 : Ssz-1;

    uint32_t sA0 = (uint32_t)__cvta_generic_to_shared(&As[0][0]) + (r0*STR + c4)*4;
    uint32_t sB0 = (uint32_t)__cvta_generic_to_shared(&Bs[0][0]) + (r0*STR + c4)*4;
    const uint32_t stage = 128*STR*4;
    const uint32_t rowsk = 64*STR*4;

    float acc[4][4][4] = {};
    int ntiles = Hsz/16;

    cpa16(sA0,         T1b + (size_t)gr0*Hsz + c4);
    cpa16(sA0 + rowsk, T1b + (size_t)gr1*Hsz + c4);
    cpa16(sB0,         Xb  + (size_t)gr0*Hsz + c4);
    cpa16(sB0 + rowsk, Xb  + (size_t)gr1*Hsz + c4);
    cp_commit();

    for (int t = 0; t < ntiles; t++) {
        int s = t & 1;
        if (t+1 < ntiles) {
            int kt = (t+1)*16;
            uint32_t ds = (t+1)&1 ? stage : 0;
            cpa16(sA0 + ds,         T1b + (size_t)gr0*Hsz + kt + c4);
            cpa16(sA0 + ds + rowsk, T1b + (size_t)gr1*Hsz + kt + c4);
            cpa16(sB0 + ds,         Xb  + (size_t)gr0*Hsz + kt + c4);
            cpa16(sB0 + ds + rowsk, Xb  + (size_t)gr1*Hsz + kt + c4);
            cp_commit();
            cp_wait<1>();
        } else {
            cp_wait<0>();
        }
        __syncthreads();
        mma_slab_128((const unsigned*)As[s], (const unsigned*)Bs[s],
                     m_off, n_off, grp, qid, acc);
        __syncthreads();
    }

    float bias = bptr[0];
    float* qb = g_q + (size_t)b*Ssz*Ssz;
    #pragma unroll
    for (int mt = 0; mt < 4; mt++) {
        int i0 = m_off + mt*16 + grp;
        #pragma unroll
        for (int nt = 0; nt < 4; nt++) {
            int j = n_off + nt*8 + qid*2;
            if (j >= Ssz) continue;
            float mj0 = mask_s[j], mj1 = mask_s[j+1];
            #pragma unroll
            for (int h = 0; h < 2; h++) {
                int i = i0 + h*8;
                if (i >= Ssz) continue;
                float mi = mask_s[i], ri = rel_s[i], ci = cont_s[i];
                float mm0 = mi*mj0, mm1 = mi*mj1;
                float a0 = (ri + acc[mt][nt][h*2+0])*mm0 + ci + bias;
                float a1 = (ri + acc[mt][nt][h*2+1])*mm1 + ci + bias;
                float q0 = mm0 / (1.f + __expf(-a0));
                float q1 = mm1 / (1.f + __expf(-a1));
                *(float2*)(qb + (size_t)i*Ssz + j) = make_float2(q0, q1);
            }
        }
    }
}

// ---------------- per-batch solve via Neumann series (split-dot, 256 thr) ---------
// qD column-stochastic => ||0.8 qD||_1 = 0.8; 48 iters -> err ~2e-5 << 1e-3.
__global__ void k_solve(float* __restrict__ out) {
    int b = blockIdx.x;
    __shared__ float Q[100][101];
    __shared__ float xv[100], part[2][100], inv[100];
    int tid = threadIdx.x;
    const float* qb = g_q + (size_t)b*Ssz*Ssz;
    for (int idx = tid; idx < Ssz*Ssz; idx += blockDim.x)
        Q[idx/100][idx%100] = qb[idx];
    __syncthreads();
    if (tid < 100) {
        float s = 0.f;
        for (int i = 0; i < 100; i++) s += Q[i][tid];
        inv[tid] = LAMBf / s;
        xv[tid]  = 1.f/Ssz;
    }
    __syncthreads();
    for (int idx = tid; idx < Ssz*Ssz; idx += blockDim.x) {
        int i = idx/100, j = idx%100;
        Q[i][j] *= inv[j];
    }
    __syncthreads();
    int half = tid / 100, i = tid % 100;   // tid<200 active
    for (int it = 0; it < 48; it++) {
        if (tid < 200) {
            float s = 0.f;
            int j0 = half*50;
            #pragma unroll 5
            for (int j = j0; j < j0+50; j++) s += Q[i][j]*xv[j];
            part[half][i] = s;
        }
        __syncthreads();
        if (tid < 100) xv[tid] = part[0][tid] + part[1][tid] + 1.f/Ssz;
        __syncthreads();
    }
    if (tid < 100) out[(size_t)b*Ssz + tid] = (1.f - LAMBf)*xv[tid];
}

// ---------------- launch ----------------
extern "C" void kernel_launch(void* const* d_in, const int* in_sizes, int n_in,
                              void* d_out, int out_size) {
    const float* X    = (const float*)d_in[0];
    const int*   mask = (const int*)  d_in[1];
    const float* Wc   = (const float*)d_in[2];
    const float* Wsim = (const float*)d_in[3];
    const float* Wrel = (const float*)d_in[4];
    const float* bm   = (const float*)d_in[5];
    float* out = (float*)d_out;

    float *drep, *wsimT, *wd, *T1;
    cudaGetSymbolAddress((void**)&drep,  g_drep);
    cudaGetSymbolAddress((void**)&wsimT, g_wsimT);
    cudaGetSymbolAddress((void**)&wd,    g_wd);
    cudaGetSymbolAddress((void**)&T1,    g_T1);

    // W_sim^T so big GEMM is NT form
    k_transpose<<<dim3(Hsz/32, Hsz/32), dim3(32, 8)>>>(Wsim, wsimT);
    // T1 = X @ W_sim   [51200,768] x [768,768]
    k_gemm_nt<<<dim3(Hsz/128, BS/128), 256>>>(X, wsimT, T1, BS, Hsz, Hsz);
    // d_rep; wd = drep @ Wrel^T  (BM=32 variant: 96 blocks)
    k_mean<<<Bsz, 256>>>(X);
    k_gemm_nt32<<<dim3(Hsz/128, Bsz/32), 256>>>(drep, Wrel, wd, Bsz, Hsz, Hsz);
    // cont & rel
    k_cont_rel<<<BS/8, 256>>>(X, Wc);
    // sim + sigmoid -> q
    k_sim_q_mma<<<Bsz, 256>>>(X, mask, bm);
    // batched solve
    k_solve<<<Bsz, 256>>>(out);
}